// round 2
// baseline (speedup 1.0000x reference)
#include <cuda_runtime.h>
#include <cstdint>

// Problem dims (fixed by the reference)
#define T_STEPS 2048
#define BATCH   64
#define HID     256
#define MROWS   (T_STEPS * BATCH)   // 131072

// Scratch: xp0 / xp1 in buf0, h1 in buf1 (128 MB each, static __device__ per harness rules)
__device__ float g_buf0[(size_t)MROWS * HID];
__device__ float g_buf1[(size_t)MROWS * HID];

// ---------------------------------------------------------------------------
// GEMM + bias:  C[M,256] = A[M,256] @ W[256,256]^T + (b1+b2)
// BM=128, BN=64, BK=16, TM=8, TN=4, 256 threads.
// ---------------------------------------------------------------------------
__global__ __launch_bounds__(256) void gemm_bias_kernel(
    const float* __restrict__ A,
    const float* __restrict__ W,      // [N,K] row-major
    const float* __restrict__ b1,
    const float* __restrict__ b2,
    float* __restrict__ C)
{
    __shared__ float As[16][132];   // [k][m], padded
    __shared__ float Ws[16][68];    // [k][n], padded

    const int tid = threadIdx.x;
    const int bm  = blockIdx.x * 128;
    const int bn  = blockIdx.y * 64;
    const int tx  = tid & 15;       // n-sub (0..15) -> 4 cols
    const int ty  = tid >> 4;       // m-sub (0..15) -> 8 rows

    const int arow = tid >> 2;      // 0..63
    const int akq  = tid & 3;       // 0..3 (float4 within 16-wide k chunk)

    float acc[8][4];
    #pragma unroll
    for (int i = 0; i < 8; i++)
        #pragma unroll
        for (int j = 0; j < 4; j++) acc[i][j] = 0.f;

    for (int k0 = 0; k0 < 256; k0 += 16) {
        // Load A tile: 128 rows x 16 k  (2 float4 per thread), store transposed
        {
            float4 v = *reinterpret_cast<const float4*>(
                &A[(size_t)(bm + arow) * 256 + k0 + akq * 4]);
            As[akq*4+0][arow] = v.x; As[akq*4+1][arow] = v.y;
            As[akq*4+2][arow] = v.z; As[akq*4+3][arow] = v.w;
            float4 v2 = *reinterpret_cast<const float4*>(
                &A[(size_t)(bm + arow + 64) * 256 + k0 + akq * 4]);
            As[akq*4+0][arow+64] = v2.x; As[akq*4+1][arow+64] = v2.y;
            As[akq*4+2][arow+64] = v2.z; As[akq*4+3][arow+64] = v2.w;
        }
        // Load W tile: 64 rows x 16 k (1 float4 per thread), store transposed
        {
            float4 v = *reinterpret_cast<const float4*>(
                &W[(size_t)(bn + arow) * 256 + k0 + akq * 4]);
            // arow here reused as n index 0..63
            Ws[akq*4+0][arow] = v.x; Ws[akq*4+1][arow] = v.y;
            Ws[akq*4+2][arow] = v.z; Ws[akq*4+3][arow] = v.w;
        }
        __syncthreads();

        #pragma unroll
        for (int k = 0; k < 16; k++) {
            float a[8], w[4];
            #pragma unroll
            for (int i = 0; i < 8; i++) a[i] = As[k][ty * 8 + i];
            #pragma unroll
            for (int j = 0; j < 4; j++) w[j] = Ws[k][tx * 4 + j];
            #pragma unroll
            for (int i = 0; i < 8; i++)
                #pragma unroll
                for (int j = 0; j < 4; j++)
                    acc[i][j] = fmaf(a[i], w[j], acc[i][j]);
        }
        __syncthreads();
    }

    float bias[4];
    #pragma unroll
    for (int j = 0; j < 4; j++) {
        int n = bn + tx * 4 + j;
        bias[j] = b1[n] + b2[n];
    }

    #pragma unroll
    for (int i = 0; i < 8; i++) {
        int row = bm + ty * 8 + i;
        float4 o;
        o.x = acc[i][0] + bias[0];
        o.y = acc[i][1] + bias[1];
        o.z = acc[i][2] + bias[2];
        o.w = acc[i][3] + bias[3];
        *reinterpret_cast<float4*>(&C[(size_t)row * 256 + bn + tx * 4]) = o;
    }
}

// ---------------------------------------------------------------------------
// Recurrent scan: one CTA per batch element, 256 threads, thread j owns h[j].
// W_hh row j: k in [0,128) lives in registers, k in [128,256) in smem
// (transposed-free: each thread reads its own row as float4, conflict-free
// via 33-float4 row stride).
// h_t = tanh(xp[t] + W_hh @ h_{t-1})
// ---------------------------------------------------------------------------
__global__ __launch_bounds__(256) void rnn_layer_kernel(
    const float* __restrict__ xp,    // [T, B, H] precomputed input + biases
    const float* __restrict__ Whh,   // [H, H] row-major
    float* __restrict__ out)         // [T, B, H]
{
    extern __shared__ float4 Ws4[];            // [256][33] float4 = 132 KB
    __shared__ __align__(16) float hbuf[HID];  // current hidden state

    const int b = blockIdx.x;
    const int j = threadIdx.x;

    // One-time: load W row j. First 128 values -> registers, rest -> smem.
    float wreg[128];
    const float4* wrow = reinterpret_cast<const float4*>(Whh + (size_t)j * HID);
    #pragma unroll
    for (int i = 0; i < 32; i++)
        reinterpret_cast<float4*>(wreg)[i] = wrow[i];
    #pragma unroll
    for (int i = 0; i < 32; i++)
        Ws4[j * 33 + i] = wrow[32 + i];

    hbuf[j] = 0.f;
    __syncthreads();

    const float4* h4    = reinterpret_cast<const float4*>(hbuf);
    const float4* wsrow = &Ws4[j * 33];
    const float*  xptr  = xp  + (size_t)b * HID + j;
    float*        optr  = out + (size_t)b * HID + j;
    const size_t  stride = (size_t)BATCH * HID;

    for (int t = 0; t < T_STEPS; t++) {
        float xv = xptr[(size_t)t * stride];   // issued early, hidden by k-loop

        float a0 = 0.f, a1 = 0.f, a2 = 0.f, a3 = 0.f;
        #pragma unroll
        for (int kk = 0; kk < 32; kk++) {      // k in [0,128): W from registers
            float4 hv = h4[kk];
            a0 = fmaf(wreg[4*kk+0], hv.x, a0);
            a1 = fmaf(wreg[4*kk+1], hv.y, a1);
            a2 = fmaf(wreg[4*kk+2], hv.z, a2);
            a3 = fmaf(wreg[4*kk+3], hv.w, a3);
        }
        #pragma unroll
        for (int kk = 0; kk < 32; kk++) {      // k in [128,256): W from smem
            float4 wv = wsrow[kk];
            float4 hv = h4[32 + kk];
            a0 = fmaf(wv.x, hv.x, a0);
            a1 = fmaf(wv.y, hv.y, a1);
            a2 = fmaf(wv.z, hv.z, a2);
            a3 = fmaf(wv.w, hv.w, a3);
        }

        float h = tanhf(xv + (a0 + a1) + (a2 + a3));

        __syncthreads();                       // all reads of old h done
        hbuf[j] = h;
        optr[(size_t)t * stride] = h;
        __syncthreads();                       // new h visible
    }
}

// ---------------------------------------------------------------------------
extern "C" void kernel_launch(void* const* d_in, const int* in_sizes, int n_in,
                              void* d_out, int out_size)
{
    const float* x     = (const float*)d_in[0];
    const float* W_ih0 = (const float*)d_in[1];
    const float* W_hh0 = (const float*)d_in[2];
    const float* b_ih0 = (const float*)d_in[3];
    const float* b_hh0 = (const float*)d_in[4];
    const float* W_ih1 = (const float*)d_in[5];
    const float* W_hh1 = (const float*)d_in[6];
    const float* b_ih1 = (const float*)d_in[7];
    const float* b_hh1 = (const float*)d_in[8];
    float* out = (float*)d_out;

    float *buf0, *buf1;
    cudaGetSymbolAddress((void**)&buf0, g_buf0);
    cudaGetSymbolAddress((void**)&buf1, g_buf1);

    const int RNN_SMEM = 256 * 33 * 16;  // 135168 B dynamic smem
    cudaFuncSetAttribute(rnn_layer_kernel,
                         cudaFuncAttributeMaxDynamicSharedMemorySize, RNN_SMEM);

    dim3 ggrid(MROWS / 128, 256 / 64);

    // Phase A: xp0 = x @ W_ih0^T + (b_ih0 + b_hh0)
    gemm_bias_kernel<<<ggrid, 256>>>(x, W_ih0, b_ih0, b_hh0, buf0);
    // Phase B: layer-1 scan -> h1
    rnn_layer_kernel<<<BATCH, 256, RNN_SMEM>>>(buf0, W_hh0, buf1);
    // Phase C: xp1 = h1 @ W_ih1^T + (b_ih1 + b_hh1)
    gemm_bias_kernel<<<ggrid, 256>>>(buf1, W_ih1, b_ih1, b_hh1, buf0);
    // Phase D: layer-2 scan -> output
    rnn_layer_kernel<<<BATCH, 256, RNN_SMEM>>>(buf0, W_hh1, out);
}